// round 15
// baseline (speedup 1.0000x reference)
#include <cuda_runtime.h>
#include <cuda_bf16.h>
#include <math.h>
#include <stdint.h>

#define NB 8
#define LQ 4096
#define LK 32768
#define DH 64
#define LKS 8000
#define UPM 8192            // upper bound for 256-padded unique count
#define GPB 256             // gather blocks per batch = UPM/32
#define NU 45
#define NUP 48
#define NCHUNK 54
#define KT 64
#define NTILES 512          // LK / KT
#define CANDMAX 1024
#define NSPLIT 64
#define KROWS 176           // smem K rows per chunk in k_M_exact
#define MARGIN 1.0f

// ---------------- device scratch ----------------
__device__ __nv_bfloat16 g_KsampH[NB * UPM * DH];
__device__ int   g_uniq[UPM];
__device__ float g_ucnt[UPM];
__device__ int   g_ucount;
__device__ int   g_upad;
__device__ float g_Kpart[NB * GPB * DH];
__device__ float g_M[NB * LQ];
__device__ int   g_top[NB * NUP];
__device__ int   g_cand[NB * CANDMAX];
__device__ float g_candP[NB * CANDMAX * NSPLIT];
__device__ int   g_ccount[NB];
__device__ float g_pm[NB * NCHUNK * NUP];
__device__ float g_pl[NB * NCHUNK * NUP];
__device__ float g_pacc[NB * NCHUNK * NUP * DH];

// ---------------- helpers ----------------
__device__ __forceinline__ void mma_bf16(float c[4], const uint32_t a[4],
                                         uint32_t b0, uint32_t b1) {
    asm volatile(
        "mma.sync.aligned.m16n8k16.row.col.f32.bf16.bf16.f32 "
        "{%0,%1,%2,%3}, {%4,%5,%6,%7}, {%8,%9}, {%0,%1,%2,%3};"
        : "+f"(c[0]), "+f"(c[1]), "+f"(c[2]), "+f"(c[3])
        : "r"(a[0]), "r"(a[1]), "r"(a[2]), "r"(a[3]), "r"(b0), "r"(b1));
}
__device__ __forceinline__ uint32_t packbf(float x, float y) {
    __nv_bfloat162 h = __floats2bfloat162_rn(x, y);
    return *(uint32_t*)&h;
}
__device__ __forceinline__ void bfsplit2(float x, float y, uint32_t& h, uint32_t& l) {
    uint32_t hh;
    asm("cvt.rn.bf16x2.f32 %0, %1, %2;" : "=r"(hh) : "f"(y), "f"(x));
    float hx = __uint_as_float(hh << 16);
    float hy = __uint_as_float(hh & 0xffff0000u);
    float rx = x - hx;
    float ry = y - hy;
    asm("cvt.rn.bf16x2.f32 %0, %1, %2;" : "=r"(l) : "f"(ry), "f"(rx));
    h = hh;
}
__device__ __forceinline__ void cp16(uint32_t dst, const void* src) {
    asm volatile("cp.async.ca.shared.global [%0], [%1], 16;\n" :: "r"(dst), "l"(src));
}
__device__ __forceinline__ void ldsm_x4(uint32_t r[4], uint32_t addr) {
    asm volatile("ldmatrix.sync.aligned.m8n8.x4.shared.b16 {%0,%1,%2,%3}, [%4];"
                 : "=r"(r[0]), "=r"(r[1]), "=r"(r[2]), "=r"(r[3]) : "r"(addr));
}
__device__ __forceinline__ void ldsm_x4_t(uint32_t r[4], uint32_t addr) {
    asm volatile("ldmatrix.sync.aligned.m8n8.x4.trans.shared.b16 {%0,%1,%2,%3}, [%4];"
                 : "=r"(r[0]), "=r"(r[1]), "=r"(r[2]), "=r"(r[3]) : "r"(addr));
}

// ---------------- kernel 0: dedupe sampled indices + counts ----------------
__global__ void k_dedup(const int* __restrict__ idx) {
    __shared__ unsigned bm[250];
    __shared__ int wo[251];
    __shared__ int hist[LKS];
    int tid = threadIdx.x;
    for (int i = tid; i < 250; i += 1024) bm[i] = 0u;
    for (int i = tid; i < LKS; i += 1024) hist[i] = 0;
    __syncthreads();
    for (int i = tid; i < LKS; i += 1024) {
        int v = idx[i];
        atomicOr(&bm[v >> 5], 1u << (v & 31));
        atomicAdd(&hist[v], 1);
    }
    __syncthreads();
    if (tid == 0) {
        int acc = 0;
        for (int w = 0; w < 250; ++w) { wo[w] = acc; acc += __popc(bm[w]); }
        wo[250] = acc;
        g_ucount = acc;
        g_upad = (acc + 255) & ~255;
    }
    __syncthreads();
    for (int w = tid; w < 250; w += 1024) {
        unsigned m = bm[w];
        int o = wo[w];
        while (m) {
            int bbit = __ffs(m) - 1;
            int v = w * 32 + bbit;
            g_uniq[o] = v;
            g_ucnt[o] = (float)hist[v];
            ++o;
            m &= m - 1;
        }
    }
    __syncthreads();
    if (tid < 256) {
        int uc = wo[250];
        int up = (uc + 255) & ~255;
        if (uc + tid < up) {
            g_uniq[uc + tid] = g_uniq[0];
            g_ucnt[uc + tid] = 0.f;
        }
    }
}

// ---------------- kernel 1: gather unique K rows -> bf16 + weighted partial ksum
__global__ __launch_bounds__(256) void k_gather(const float* __restrict__ K) {
    __shared__ float red[32][65];
    const int tid = threadIdx.x;
    const int t = blockIdx.x * 256 + tid;
    const int chunk = t & 7;
    const int rest = t >> 3;
    const int j = rest % UPM;
    const int b = rest / UPM;
    const int r = tid >> 3;
    const int upad = g_upad;
    const int uc = g_ucount;

    float v[8];
#pragma unroll
    for (int d = 0; d < 8; ++d) v[d] = 0.f;
    float w = 0.f;

    if (j < upad) {
        int src = g_uniq[j];
        const float4* p = (const float4*)(K + ((size_t)b * LK + src) * DH + chunk * 8);
        float4 v0 = p[0], v1 = p[1];
        v[0] = v0.x; v[1] = v0.y; v[2] = v0.z; v[3] = v0.w;
        v[4] = v1.x; v[5] = v1.y; v[6] = v1.z; v[7] = v1.w;
        uint4 wq = make_uint4(packbf(v0.x, v0.y), packbf(v0.z, v0.w),
                              packbf(v1.x, v1.y), packbf(v1.z, v1.w));
        *(uint4*)(g_KsampH + ((size_t)(b * UPM) + j) * DH + chunk * 8) = wq;
        if (j < uc) w = g_ucnt[j];
    }
#pragma unroll
    for (int d = 0; d < 8; ++d) red[r][chunk * 8 + d] = w * v[d];
    __syncthreads();
    if (tid < 64) {
        float s = 0.f;
#pragma unroll 8
        for (int rr = 0; rr < 32; ++rr) s += red[rr][tid];
        g_Kpart[((size_t)b * GPB + (blockIdx.x % GPB)) * DH + tid] = s;
    }
}

// ---------------- kernel 3: approx M via bf16 mma, m128 x 256-key tiles ----
__global__ __launch_bounds__(256, 2) void k_M_mma(const float* __restrict__ q) {
    __shared__ __nv_bfloat16 Bs[2][256 * 72];
    __shared__ float rowmaxS[4][128];
    __shared__ float ksumS[64];

    const int tid  = threadIdx.x;
    const int wid  = tid >> 5;
    const int lane = tid & 31;
    const int gid  = lane >> 2;
    const int tig  = lane & 3;
    const int b    = blockIdx.y;
    const int m0   = blockIdx.x * 128;
    const int mhalf = (wid & 1) * 64;
    const int nquad = wid >> 1;           // 0..3 -> keys [64*nquad, +64)

    if (tid < 64) {
        float s = 0.f;
        for (int i = 0; i < GPB; ++i) s += g_Kpart[((size_t)b * GPB + i) * DH + tid];
        ksumS[tid] = s;
    }

    uint32_t a[4][4][4];
#pragma unroll
    for (int mb = 0; mb < 4; ++mb) {
        int r0 = m0 + mhalf + mb * 16 + gid;
        int r1 = r0 + 8;
        const float* q0 = q + ((size_t)(b * LQ) + r0) * DH;
        const float* q1 = q + ((size_t)(b * LQ) + r1) * DH;
#pragma unroll
        for (int kk = 0; kk < 4; ++kk) {
            int c = kk * 16 + 2 * tig;
            float2 x0 = *(const float2*)(q0 + c);
            float2 x1 = *(const float2*)(q1 + c);
            float2 x2 = *(const float2*)(q0 + c + 8);
            float2 x3 = *(const float2*)(q1 + c + 8);
            a[mb][kk][0] = packbf(x0.x, x0.y);
            a[mb][kk][1] = packbf(x1.x, x1.y);
            a[mb][kk][2] = packbf(x2.x, x2.y);
            a[mb][kk][3] = packbf(x3.x, x3.y);
        }
    }

    const int niter = g_upad >> 8;        // tiles of 256 keys
    uint32_t sBase = (uint32_t)__cvta_generic_to_shared(&Bs[0][0]);

    uint32_t rowoff[8];
#pragma unroll
    for (int nc = 0; nc < 8; ++nc) {
        int row = nquad * 64 + nc * 8 + (lane & 7);
        rowoff[nc] = (uint32_t)(row * 144 + (lane >> 3) * 16);
    }

    {   // prologue: tile 0 (256 rows)
#pragma unroll
        for (int it2 = 0; it2 < 4; ++it2) {
            int unit = tid + 256 * it2;
            int row = unit >> 2, seg = unit & 3;
            const __nv_bfloat16* src = g_KsampH + ((size_t)(b * UPM) + row) * DH + seg * 16;
            uint32_t dst = sBase + row * 144 + seg * 32;
            cp16(dst, src);
            cp16(dst + 16, src + 8);
        }
    }
    asm volatile("cp.async.commit_group;\n");

    float rmax[4][2];
#pragma unroll
    for (int mb = 0; mb < 4; ++mb) { rmax[mb][0] = -INFINITY; rmax[mb][1] = -INFINITY; }

    for (int t = 0; t < niter; ++t) {
        asm volatile("cp.async.wait_group 0;\n");
        __syncthreads();
        if (t + 1 < niter) {
#pragma unroll
            for (int it2 = 0; it2 < 4; ++it2) {
                int unit = tid + 256 * it2;
                int row = unit >> 2, seg = unit & 3;
                const __nv_bfloat16* src =
                    g_KsampH + ((size_t)(b * UPM) + (t + 1) * 256 + row) * DH + seg * 16;
                uint32_t dst = sBase + ((t + 1) & 1) * 36864 + row * 144 + seg * 32;
                cp16(dst, src);
                cp16(dst + 16, src + 8);
            }
        }
        asm volatile("cp.async.commit_group;\n");

        uint32_t bufBase = sBase + (t & 1) * 36864;
#pragma unroll
        for (int nc = 0; nc < 8; ++nc) {
            uint32_t addr0 = bufBase + rowoff[nc];
            uint32_t bk[4], bk2[4];
            ldsm_x4(bk,  addr0);
            ldsm_x4(bk2, addr0 + 64);
#pragma unroll
            for (int mb = 0; mb < 4; ++mb) {
                float acc[4] = {0.f, 0.f, 0.f, 0.f};
                mma_bf16(acc, a[mb][0], bk[0],  bk[1]);
                mma_bf16(acc, a[mb][1], bk[2],  bk[3]);
                mma_bf16(acc, a[mb][2], bk2[0], bk2[1]);
                mma_bf16(acc, a[mb][3], bk2[2], bk2[3]);
                rmax[mb][0] = fmaxf(rmax[mb][0], fmaxf(acc[0], acc[1]));
                rmax[mb][1] = fmaxf(rmax[mb][1], fmaxf(acc[2], acc[3]));
            }
        }
    }

#pragma unroll
    for (int mb = 0; mb < 4; ++mb)
#pragma unroll
        for (int h = 0; h < 2; ++h) {
            rmax[mb][h] = fmaxf(rmax[mb][h], __shfl_xor_sync(0xffffffffu, rmax[mb][h], 1));
            rmax[mb][h] = fmaxf(rmax[mb][h], __shfl_xor_sync(0xffffffffu, rmax[mb][h], 2));
        }
    if (tig == 0) {
#pragma unroll
        for (int mb = 0; mb < 4; ++mb) {
            rowmaxS[nquad][mhalf + mb * 16 + gid]     = rmax[mb][0];
            rowmaxS[nquad][mhalf + mb * 16 + gid + 8] = rmax[mb][1];
        }
    }
    __syncthreads();

    if (tid < 128) {
        int m = m0 + tid;
        float mx = fmaxf(fmaxf(rowmaxS[0][tid], rowmaxS[1][tid]),
                         fmaxf(rowmaxS[2][tid], rowmaxS[3][tid]));
        const float* qp = q + ((size_t)(b * LQ) + m) * DH;
        float d0 = 0.f, d1 = 0.f, d2 = 0.f, d3 = 0.f;
#pragma unroll
        for (int d = 0; d < 64; d += 4) {
            d0 += qp[d]     * ksumS[d];
            d1 += qp[d + 1] * ksumS[d + 1];
            d2 += qp[d + 2] * ksumS[d + 2];
            d3 += qp[d + 3] * ksumS[d + 3];
        }
        g_M[b * LQ + m] = mx - ((d0 + d1) + (d2 + d3)) * (1.0f / (float)LKS);
    }
}

// ---------------- kernel 4: histogram threshold + candidate collect --------
__global__ __launch_bounds__(512) void k_thresh() {
    const int b = blockIdx.x;
    const int tid = threadIdx.x;
    __shared__ float sv[LQ];
    __shared__ int hist[512];
    __shared__ float wmn[16], wmx[16];
    __shared__ float s_mn, s_range, s_thresh;
    __shared__ int s_cnt;

    float mn = INFINITY, mx = -INFINITY;
    for (int j = tid; j < LQ; j += 512) {
        float v = g_M[b * LQ + j];
        sv[j] = v;
        mn = fminf(mn, v);
        mx = fmaxf(mx, v);
    }
#pragma unroll
    for (int off = 16; off > 0; off >>= 1) {
        mn = fminf(mn, __shfl_xor_sync(0xffffffffu, mn, off));
        mx = fmaxf(mx, __shfl_xor_sync(0xffffffffu, mx, off));
    }
    if ((tid & 31) == 0) { wmn[tid >> 5] = mn; wmx[tid >> 5] = mx; }
    if (tid < 512) hist[tid] = 0;
    if (tid == 0) s_cnt = 0;
    __syncthreads();
    if (tid == 0) {
        float a = INFINITY, z = -INFINITY;
        for (int g = 0; g < 16; ++g) { a = fminf(a, wmn[g]); z = fmaxf(z, wmx[g]); }
        s_mn = a;
        s_range = z - a + 1e-6f;
    }
    __syncthreads();
    const float scale = 511.0f / s_range;
    for (int j = tid; j < LQ; j += 512) {
        int bin = (int)((sv[j] - s_mn) * scale);
        bin = max(0, min(511, bin));
        atomicAdd(&hist[bin], 1);
    }
    __syncthreads();
    if (tid == 0) {
        int cum = 0, bsel = 511;
        for (int i = 0; i < 512; ++i) {
            cum += hist[i];
            if (cum >= NU) { bsel = i; break; }
        }
        s_thresh = s_mn + (float)(bsel + 1) * (s_range / 511.0f) + MARGIN;
    }
    __syncthreads();
    const float th = s_thresh;
    for (int j = tid; j < LQ; j += 512) {
        if (sv[j] <= th) {
            int p = atomicAdd(&s_cnt, 1);
            if (p < CANDMAX) g_cand[b * CANDMAX + p] = j;
        }
    }
    __syncthreads();
    if (tid == 0) g_ccount[b] = min(s_cnt, CANDMAX);
}

// ---------------- kernel 5: exact fp32 max (split-K over unique keys) ------
__global__ __launch_bounds__(256) void k_M_exact(const float* __restrict__ q,
                                                 const float* __restrict__ K) {
    extern __shared__ float sh[];
    float* Kc = sh;                       // [KROWS][68]
    float* Qc = sh + KROWS * 68;          // [128][68]

    const int b = blockIdx.y;
    const int sp = blockIdx.x;
    const int tid = threadIdx.x;
    const int wid = tid >> 5;
    const int lane = tid & 31;

    const int uc = g_ucount;
    const int j0 = (sp * uc) / NSPLIT;
    const int j1 = ((sp + 1) * uc) / NSPLIT;
    const int cnt = g_ccount[b];

    for (int kc = j0, first = 1; kc < j1; kc += KROWS, first = 0) {
        const int nr = min(KROWS, j1 - kc);
        __syncthreads();
        for (int i = tid; i < nr * 16; i += 256) {
            int r = i >> 4, d4 = i & 15;
            int src = g_uniq[kc + r];
            *(float4*)&Kc[r * 68 + 4 * d4] =
                *(const float4*)(K + ((size_t)b * LK + src) * DH + 4 * d4);
        }

        for (int cg = 0; cg < cnt; cg += 128) {
            int ncg = min(128, cnt - cg);
            __syncthreads();
            for (int i = tid; i < ncg * 16; i += 256) {
                int c = i >> 4, d4 = i & 15;
                int qi = g_cand[b * CANDMAX + cg + c];
                *(float4*)&Qc[c * 68 + 4 * d4] =
                    *(const float4*)(q + ((size_t)(b * LQ) + qi) * DH + 4 * d4);
            }
            __syncthreads();
            for (int c = wid; c < ncg; c += 8) {
                const float* qr = &Qc[c * 68];
                float mx = -INFINITY;
                for (int r = lane; r < nr; r += 32) {
                    const float* kr = &Kc[r * 68];
                    float a0 = 0.f, a1 = 0.f, a2 = 0.f, a3 = 0.f;
#pragma unroll
                    for (int d4 = 0; d4 < 16; ++d4) {
                        float4 kv = *(const float4*)&kr[4 * d4];
                        float4 qv = *(const float4*)&qr[4 * d4];
                        a0 += qv.x * kv.x;
                        a1 += qv.y * kv.y;
                        a2 += qv.z * kv.z;
                        a3 += qv.w * kv.w;
                    }
                    mx = fmaxf(mx, (a0 + a1) + (a2 + a3));
                }
#pragma unroll
                for (int off = 16; off > 0; off >>= 1)
                    mx = fmaxf(mx, __shfl_xor_sync(0xffffffffu, mx, off));
                if (lane == 0) {
                    float* slot = &g_candP[((size_t)(b * CANDMAX) + cg + c) * NSPLIT + sp];
                    *slot = first ? mx : fmaxf(*slot, mx);
                }
            }
        }
    }
}

// ---------------- kernel 6: finalize exact M + top-45 selection ------------
__global__ __launch_bounds__(256) void k_select(const float* __restrict__ q) {
    const int b = blockIdx.x;
    const int tid = threadIdx.x;
    __shared__ float cv[CANDMAX];
    __shared__ int   ci[CANDMAX];
    __shared__ float ksumS[64];
    const int cnt = g_ccount[b];

    if (tid < 64) {
        float s = 0.f;
        for (int i = 0; i < GPB; ++i) s += g_Kpart[((size_t)b * GPB + i) * DH + tid];
        ksumS[tid] = s;
    }
    __syncthreads();

    for (int c = tid; c < CANDMAX; c += 256) {
        if (c < cnt) {
            float mx = -INFINITY;
#pragma unroll
            for (int s = 0; s < NSPLIT; ++s)
                mx = fmaxf(mx, g_candP[((size_t)(b * CANDMAX) + c) * NSPLIT + s]);
            int qi = g_cand[b * CANDMAX + c];
            const float* qp = q + ((size_t)(b * LQ) + qi) * DH;
            float dot = 0.f;
            for (int d = 0; d < 64; ++d) dot += qp[d] * ksumS[d];
            cv[c] = mx - dot * (1.0f / (float)LKS);
            ci[c] = qi;
        } else {
            cv[c] = INFINITY;
            ci[c] = 1 << 30;
        }
    }
    __syncthreads();

    if (tid < 32) {
        for (int it = 0; it < NU; ++it) {
            float best = INFINITY; int bidx = 1 << 30; int bslot = 0;
            for (int j = tid; j < CANDMAX; j += 32) {
                float v = cv[j]; int qi2 = ci[j];
                if (v < best || (v == best && qi2 < bidx)) { best = v; bidx = qi2; bslot = j; }
            }
#pragma unroll
            for (int off = 16; off > 0; off >>= 1) {
                float v2 = __shfl_xor_sync(0xffffffffu, best, off);
                int   i2 = __shfl_xor_sync(0xffffffffu, bidx, off);
                int   s2 = __shfl_xor_sync(0xffffffffu, bslot, off);
                if (v2 < best || (v2 == best && i2 < bidx)) { best = v2; bidx = i2; bslot = s2; }
            }
            if (tid == 0) { g_top[b * NUP + it] = bidx; cv[bslot] = INFINITY; }
            __syncwarp();
        }
        if (tid < NUP - NU) g_top[b * NUP + NU + tid] = 0;
    }
}

// ---------------- kernel 7: bf16x2-Karatsuba mma attention (single wave) ---
__global__ __launch_bounds__(256, 3) void k_attn(const float* __restrict__ q,
                                                 const float* __restrict__ K,
                                                 const float* __restrict__ V,
                                                 float* __restrict__ out_s) {
    extern __shared__ char smc[];
    __nv_bfloat16* Qh = (__nv_bfloat16*)smc;            // 48*72
    __nv_bfloat16* Ql = Qh + 48 * 72;
    __nv_bfloat16* Kh = Ql + 48 * 72;                   // 64*72
    __nv_bfloat16* Kl = Kh + 64 * 72;
    __nv_bfloat16* Vh = Kl + 64 * 72;                   // 64*72 rows=key
    __nv_bfloat16* Vl = Vh + 64 * 72;
    char* Ub = (char*)(Vl + 64 * 72);                   // union, 13824 B
    float* SP = (float*)Ub;                             // [48][68] f32
    __nv_bfloat16* Ph = (__nv_bfloat16*)Ub;             // [48][72]
    __nv_bfloat16* Pl = Ph + 48 * 72;
    float* fS = (float*)(Ub + 13824);                   // [48]

    const uint32_t sQh = (uint32_t)__cvta_generic_to_shared(Qh);
    const uint32_t sQl = (uint32_t)__cvta_generic_to_shared(Ql);
    const uint32_t sKh = (uint32_t)__cvta_generic_to_shared(Kh);
    const uint32_t sKl = (uint32_t)__cvta_generic_to_shared(Kl);
    const uint32_t sVh = (uint32_t)__cvta_generic_to_shared(Vh);
    const uint32_t sVl = (uint32_t)__cvta_generic_to_shared(Vl);
    const uint32_t sPh = (uint32_t)__cvta_generic_to_shared(Ph);
    const uint32_t sPl = (uint32_t)__cvta_generic_to_shared(Pl);

    const int tid = threadIdx.x;
    const int ty = tid >> 5;
    const int tx = tid & 31;
    const int gid = tx >> 2;
    const int tig = tx & 3;
    const int b = blockIdx.y;
    const int chunk = blockIdx.x;
    const int t0 = (chunk * NTILES) / NCHUNK;
    const int t1 = ((chunk + 1) * NTILES) / NCHUNK;

#pragma unroll
    for (int i = 0; i < 3; ++i) {
        int fidx = tid + 256 * i;
        int u    = fidx >> 4;
        int d4   = fidx & 15;
        float4 v = make_float4(0.f, 0.f, 0.f, 0.f);
        if (u < NU) {
            int qi = g_top[b * NUP + u];
            v = *(const float4*)(q + ((size_t)(b * LQ + qi)) * DH + 4 * d4);
        }
        uint32_t h0, l0, h1, l1;
        bfsplit2(v.x, v.y, h0, l0);
        bfsplit2(v.z, v.w, h1, l1);
        *(uint32_t*)(Qh + u * 72 + 4 * d4)     = h0;
        *(uint32_t*)(Qh + u * 72 + 4 * d4 + 2) = h1;
        *(uint32_t*)(Ql + u * 72 + 4 * d4)     = l0;
        *(uint32_t*)(Ql + u * 72 + 4 * d4 + 2) = l1;
    }

    float mrun[6], lrun[6];
#pragma unroll
    for (int i = 0; i < 6; ++i) { mrun[i] = -INFINITY; lrun[i] = 0.f; }
    float oc[3][4];
#pragma unroll
    for (int mt = 0; mt < 3; ++mt)
#pragma unroll
        for (int i = 0; i < 4; ++i) oc[mt][i] = 0.f;

    for (int kt = t0; kt < t1; ++kt) {
        const int kg0 = kt * KT;
        __syncthreads();
#pragma unroll
        for (int i = 0; i < 4; ++i) {
            int fidx = tid + 256 * i;
            int k    = fidx >> 4;
            int d4   = fidx & 15;
            float4 kv = *(const float4*)(K + ((size_t)(b * LK + kg0 + k)) * DH + 4 * d4);
            uint32_t h0, l0, h1, l1;
            bfsplit2(kv.x, kv.y, h0, l0);
            bfsplit2(kv.z, kv.w, h1, l1);
            *(uint32_t*)(Kh + k * 72 + 4 * d4)     = h0;
            *(uint32_t*)(Kh + k * 72 + 4 * d4 + 2) = h1;
            *(uint32_t*)(Kl + k * 72 + 4 * d4)     = l0;
            *(uint32_t*)(Kl + k * 72 + 4 * d4 + 2) = l1;
            float4 vv = *(const float4*)(V + ((size_t)(b * LK + kg0 + k)) * DH + 4 * d4);
            bfsplit2(vv.x, vv.y, h0, l0);
            bfsplit2(vv.z, vv.w, h1, l1);
            *(uint32_t*)(Vh + k * 72 + 4 * d4)     = h0;
            *(uint32_t*)(Vh + k * 72 + 4 * d4 + 2) = h1;
            *(uint32_t*)(Vl + k * 72 + 4 * d4)     = l0;
            *(uint32_t*)(Vl + k * 72 + 4 * d4 + 2) = l1;
        }
        __syncthreads();

        {
            uint32_t bh[8], bl[8];
            uint32_t kaddr = sKh + (uint32_t)((8 * ty + (tx & 7)) * 144 + (tx >> 3) * 16);
            ldsm_x4(bh,     kaddr);
            ldsm_x4(bh + 4, kaddr + 64);
            kaddr = sKl + (uint32_t)((8 * ty + (tx & 7)) * 144 + (tx >> 3) * 16);
            ldsm_x4(bl,     kaddr);
            ldsm_x4(bl + 4, kaddr + 64);

#pragma unroll
            for (int mt = 0; mt < 3; ++mt) {
                float accS[4] = {0.f, 0.f, 0.f, 0.f};
                uint32_t arow = (uint32_t)((mt * 16 + (tx & 15)) * 144 + (tx >> 4) * 16);
#pragma unroll
                for (int ks = 0; ks < 4; ++ks) {
                    uint32_t ah[4], al[4];
                    ldsm_x4(ah, sQh + arow + ks * 32);
                    ldsm_x4(al, sQl + arow + ks * 32);
                    mma_bf16(accS, ah, bh[2 * ks], bh[2 * ks + 1]);
                    mma_bf16(accS, ah, bl[2 * ks], bl[2 * ks + 1]);
                    mma_bf16(accS, al, bh[2 * ks], bh[2 * ks + 1]);
                }
                int r0 = mt * 16 + gid;
                *(float2*)&SP[r0 * 68 + 8 * ty + 2 * tig] =
                    make_float2(accS[0] * 0.125f, accS[1] * 0.125f);
                *(float2*)&SP[(r0 + 8) * 68 + 8 * ty + 2 * tig] =
                    make_float2(accS[2] * 0.125f, accS[3] * 0.125f);
            }
        }
        __syncthreads();

        float pr[6][2], fnew[6];
#pragma unroll
        for (int i = 0; i < 6; ++i) {
            int u = 6 * ty + i;
            float2 sv = *(const float2*)&SP[u * 68 + 2 * tx];
            float mx = fmaxf(sv.x, sv.y);
#pragma unroll
            for (int off = 16; off > 0; off >>= 1)
                mx = fmaxf(mx, __shfl_xor_sync(0xffffffffu, mx, off));
            float mn = fmaxf(mrun[i], mx);
            float f  = __expf(mrun[i] - mn);
            float p0 = __expf(sv.x - mn);
            float p1 = __expf(sv.y - mn);
            float ps = p0 + p1;
#pragma unroll
            for (int off = 16; off > 0; off >>= 1)
                ps += __shfl_xor_sync(0xffffffffu, ps, off);
            lrun[i] = lrun[i] * f + ps;
            mrun[i] = mn;
            fnew[i] = f;
            pr[i][0] = p0; pr[i][1] = p1;
            if (u < NU)
                *(float2*)(out_s + ((size_t)(b * NU + u)) * LK + kg0 + 2 * tx) = sv;
        }
        __syncthreads();

#pragma unroll
        for (int i = 0; i < 6; ++i) {
            int u = 6 * ty + i;
            uint32_t h, l;
            bfsplit2(pr[i][0], pr[i][1], h, l);
            *(uint32_t*)(Ph + u * 72 + 2 * tx) = h;
            *(uint32_t*)(Pl + u * 72 + 2 * tx) = l;
            if (tx == 0) fS[u] = fnew[i];
        }
        __syncthreads();

        {
            uint32_t bh[8], bl[8];
            uint32_t vaddr = sVh + (uint32_t)(tx * 144 + 16 * ty);
            ldsm_x4_t(bh,     vaddr);
            ldsm_x4_t(bh + 4, vaddr + 32 * 144);
            vaddr = sVl + (uint32_t)(tx * 144 + 16 * ty);
            ldsm_x4_t(bl,     vaddr);
            ldsm_x4_t(bl + 4, vaddr + 32 * 144);

#pragma unroll
            for (int mt = 0; mt < 3; ++mt) {
                float f0 = fS[mt * 16 + gid];
                float f1 = fS[mt * 16 + gid + 8];
                oc[mt][0] *= f0; oc[mt][1] *= f0;
                oc[mt][2] *= f1; oc[mt][3] *= f1;
                uint32_t arow = (uint32_t)((mt * 16 + (tx & 15)) * 144 + (tx >> 4) * 16);
#pragma unroll
                for (int ks = 0; ks < 4; ++ks) {
                    uint32_t ph[4], pl2[4];
                    ldsm_x4(ph,  sPh + arow + ks * 32);
                    ldsm_x4(pl2, sPl + arow + ks * 32);
                    mma_bf16(oc[mt], ph,  bh[2 * ks], bh[2 * ks + 1]);
                    mma_bf16(oc[mt], ph,  bl[2 * ks], bl[2 * ks + 1]);
                    mma_bf16(oc[mt], pl2, bh[2 * ks], bh[2 * ks + 1]);
                }
            }
        }
    }

    if (tx == 0) {
#pragma unroll
        for (int i = 0; i < 6; ++i) {
            int u = 6 * ty + i;
            g_pm[(b * NCHUNK + chunk) * NUP + u] = mrun[i];
            g_pl[(b * NCHUNK + chunk) * NUP + u] = lrun[i];
        }
    }
#pragma unroll
    for (int mt = 0; mt < 3; ++mt) {
        int r0 = mt * 16 + gid;
        *(float2*)&g_pacc[((size_t)(b * NCHUNK + chunk) * NUP + r0) * DH + 8 * ty + 2 * tig] =
            make_float2(oc[mt][0], oc[mt][1]);
        *(float2*)&g_pacc[((size_t)(b * NCHUNK + chunk) * NUP + r0 + 8) * DH + 8 * ty + 2 * tig] =
            make_float2(oc[mt][2], oc[mt][3]);
    }
}

// ---------------- kernel 8: combine split-softmax partials ----------------
__global__ void k_combine(float* __restrict__ out_o) {
    int u = blockIdx.x;
    int b = blockIdx.y;
    int d = threadIdx.x;
    float gm = -INFINITY;
    for (int c = 0; c < NCHUNK; ++c)
        gm = fmaxf(gm, g_pm[(b * NCHUNK + c) * NUP + u]);
    float L = 0.f, a = 0.f;
    for (int c = 0; c < NCHUNK; ++c) {
        float w = __expf(g_pm[(b * NCHUNK + c) * NUP + u] - gm);
        L += g_pl[(b * NCHUNK + c) * NUP + u] * w;
        a += g_pacc[((size_t)(b * NCHUNK + c) * NUP + u) * DH + d] * w;
    }
    out_o[(b * NU + u) * DH + d] = a / L;
}

// ---------------- launch ----------------
extern "C" void kernel_launch(void* const* d_in, const int* in_sizes, int n_in,
                              void* d_out, int out_size) {
    const float* q  = (const float*)d_in[0];
    const float* K  = (const float*)d_in[1];
    const float* V  = (const float*)d_in[2];
    const int* idx  = (const int*)d_in[3];
    float* out_o = (float*)d_out;                  // attn_output [8,45,64]
    float* out_s = out_o + NB * NU * DH;           // attn_scores [8,45,32768]

    (void)in_sizes; (void)n_in; (void)out_size;

    const int smem_attn  = 48 * 72 * 2 * 2 + 64 * 72 * 2 * 2 * 2 + 13824 + 192;  // 64704
    const int smem_exact = (KROWS * 68 + 128 * 68) * 4;                          // 82688
    cudaFuncSetAttribute(k_attn,    cudaFuncAttributeMaxDynamicSharedMemorySize, smem_attn);
    cudaFuncSetAttribute(k_M_exact, cudaFuncAttributeMaxDynamicSharedMemorySize, smem_exact);

    k_dedup<<<1, 1024>>>(idx);
    k_gather<<<NB * GPB, 256>>>(K);
    k_M_mma<<<dim3(LQ / 128, NB), 256>>>(q);
    k_thresh<<<NB, 512>>>();
    k_M_exact<<<dim3(NSPLIT, NB), 256, smem_exact>>>(q, K);
    k_select<<<NB, 256>>>(q);
    k_attn<<<dim3(NCHUNK, NB), 256, smem_attn>>>(q, K, V, out_s);
    k_combine<<<dim3(NU, NB), 64>>>(out_o);
}

// round 16
// speedup vs baseline: 1.0499x; 1.0499x over previous
#include <cuda_runtime.h>
#include <cuda_bf16.h>
#include <math.h>
#include <stdint.h>

#define NB 8
#define LQ 4096
#define LK 32768
#define DH 64
#define LKS 8000
#define UPM 8064            // upper bound for 128-padded unique count
#define GPB 252             // gather blocks per batch = UPM/32
#define NU 45
#define NUP 48
#define NCHUNK 54
#define KT 64
#define NTILES 512          // LK / KT
#define CANDMAX 1024
#define NSPLIT 32
#define KROWS 176           // smem K rows per chunk in k_M_exact
#define MARGIN 1.0f

// ---------------- device scratch ----------------
__device__ __nv_bfloat16 g_KsampH[NB * UPM * DH];
__device__ int   g_uniq[UPM];
__device__ float g_ucnt[UPM];
__device__ int   g_ucount;
__device__ int   g_upad;
__device__ float g_Kpart[NB * GPB * DH];
__device__ float g_M[NB * LQ];
__device__ int   g_top[NB * NUP];
__device__ int   g_cand[NB * CANDMAX];
__device__ float g_candP[NB * CANDMAX * NSPLIT];
__device__ int   g_ccount[NB];
__device__ float g_pm[NB * NCHUNK * NUP];
__device__ float g_pl[NB * NCHUNK * NUP];
__device__ float g_pacc[NB * NCHUNK * NUP * DH];

// ---------------- helpers ----------------
__device__ __forceinline__ void mma_bf16(float c[4], const uint32_t a[4],
                                         uint32_t b0, uint32_t b1) {
    asm volatile(
        "mma.sync.aligned.m16n8k16.row.col.f32.bf16.bf16.f32 "
        "{%0,%1,%2,%3}, {%4,%5,%6,%7}, {%8,%9}, {%0,%1,%2,%3};"
        : "+f"(c[0]), "+f"(c[1]), "+f"(c[2]), "+f"(c[3])
        : "r"(a[0]), "r"(a[1]), "r"(a[2]), "r"(a[3]), "r"(b0), "r"(b1));
}
__device__ __forceinline__ uint32_t packbf(float x, float y) {
    __nv_bfloat162 h = __floats2bfloat162_rn(x, y);
    return *(uint32_t*)&h;
}
// fast split: 2 packed cvts + bit-unpack hi + 2 subs (identical rounding to scalar path)
__device__ __forceinline__ void bfsplit2(float x, float y, uint32_t& h, uint32_t& l) {
    uint32_t hh;
    asm("cvt.rn.bf16x2.f32 %0, %1, %2;" : "=r"(hh) : "f"(y), "f"(x));
    float hx = __uint_as_float(hh << 16);
    float hy = __uint_as_float(hh & 0xffff0000u);
    float rx = x - hx;
    float ry = y - hy;
    asm("cvt.rn.bf16x2.f32 %0, %1, %2;" : "=r"(l) : "f"(ry), "f"(rx));
    h = hh;
}
__device__ __forceinline__ void cp16(uint32_t dst, const void* src) {
    asm volatile("cp.async.ca.shared.global [%0], [%1], 16;\n" :: "r"(dst), "l"(src));
}
__device__ __forceinline__ void ldsm_x4(uint32_t r[4], uint32_t addr) {
    asm volatile("ldmatrix.sync.aligned.m8n8.x4.shared.b16 {%0,%1,%2,%3}, [%4];"
                 : "=r"(r[0]), "=r"(r[1]), "=r"(r[2]), "=r"(r[3]) : "r"(addr));
}
__device__ __forceinline__ void ldsm_x4_t(uint32_t r[4], uint32_t addr) {
    asm volatile("ldmatrix.sync.aligned.m8n8.x4.trans.shared.b16 {%0,%1,%2,%3}, [%4];"
                 : "=r"(r[0]), "=r"(r[1]), "=r"(r[2]), "=r"(r[3]) : "r"(addr));
}

// ---------------- kernel 0: dedupe sampled indices + counts ----------------
__global__ void k_dedup(const int* __restrict__ idx) {
    __shared__ unsigned bm[250];
    __shared__ int wo[251];
    __shared__ int hist[LKS];
    int tid = threadIdx.x;
    for (int i = tid; i < 250; i += 1024) bm[i] = 0u;
    for (int i = tid; i < LKS; i += 1024) hist[i] = 0;
    __syncthreads();
    for (int i = tid; i < LKS; i += 1024) {
        int v = idx[i];
        atomicOr(&bm[v >> 5], 1u << (v & 31));
        atomicAdd(&hist[v], 1);
    }
    __syncthreads();
    if (tid == 0) {
        int acc = 0;
        for (int w = 0; w < 250; ++w) { wo[w] = acc; acc += __popc(bm[w]); }
        wo[250] = acc;
        g_ucount = acc;
        g_upad = (acc + 127) & ~127;
    }
    __syncthreads();
    for (int w = tid; w < 250; w += 1024) {
        unsigned m = bm[w];
        int o = wo[w];
        while (m) {
            int bbit = __ffs(m) - 1;
            int v = w * 32 + bbit;
            g_uniq[o] = v;
            g_ucnt[o] = (float)hist[v];
            ++o;
            m &= m - 1;
        }
    }
    __syncthreads();
    if (tid < 128) {
        int uc = wo[250];
        int up = (uc + 127) & ~127;
        if (uc + tid < up) {
            g_uniq[uc + tid] = g_uniq[0];
            g_ucnt[uc + tid] = 0.f;
        }
    }
}

// ---------------- kernel 1: gather unique K rows -> bf16 + weighted partial ksum
__global__ __launch_bounds__(256) void k_gather(const float* __restrict__ K) {
    __shared__ float red[32][65];
    const int tid = threadIdx.x;
    const int t = blockIdx.x * 256 + tid;
    const int chunk = t & 7;
    const int rest = t >> 3;
    const int j = rest % UPM;
    const int b = rest / UPM;
    const int r = tid >> 3;
    const int upad = g_upad;
    const int uc = g_ucount;

    float v[8];
#pragma unroll
    for (int d = 0; d < 8; ++d) v[d] = 0.f;
    float w = 0.f;

    if (j < upad) {
        int src = g_uniq[j];
        const float4* p = (const float4*)(K + ((size_t)b * LK + src) * DH + chunk * 8);
        float4 v0 = p[0], v1 = p[1];
        v[0] = v0.x; v[1] = v0.y; v[2] = v0.z; v[3] = v0.w;
        v[4] = v1.x; v[5] = v1.y; v[6] = v1.z; v[7] = v1.w;
        uint4 wq = make_uint4(packbf(v0.x, v0.y), packbf(v0.z, v0.w),
                              packbf(v1.x, v1.y), packbf(v1.z, v1.w));
        *(uint4*)(g_KsampH + ((size_t)(b * UPM) + j) * DH + chunk * 8) = wq;
        if (j < uc) w = g_ucnt[j];
    }
#pragma unroll
    for (int d = 0; d < 8; ++d) red[r][chunk * 8 + d] = w * v[d];
    __syncthreads();
    if (tid < 64) {
        float s = 0.f;
#pragma unroll 8
        for (int rr = 0; rr < 32; ++rr) s += red[rr][tid];
        g_Kpart[((size_t)b * GPB + (blockIdx.x % GPB)) * DH + tid] = s;
    }
}

// ---------------- kernel 3: approx M via bf16 mma, m128 x 128-key tiles ----
__global__ __launch_bounds__(256, 2) void k_M_mma(const float* __restrict__ q) {
    __shared__ __nv_bfloat16 Bs[2][128 * 72];
    __shared__ float rowmaxS[4][128];
    __shared__ float ksumS[64];

    const int tid  = threadIdx.x;
    const int wid  = tid >> 5;
    const int lane = tid & 31;
    const int gid  = lane >> 2;
    const int tig  = lane & 3;
    const int b    = blockIdx.y;
    const int m0   = blockIdx.x * 128;
    const int mhalf = (wid & 1) * 64;
    const int nquad = wid >> 1;

    if (tid < 64) {
        float s = 0.f;
        for (int i = 0; i < GPB; ++i) s += g_Kpart[((size_t)b * GPB + i) * DH + tid];
        ksumS[tid] = s;
    }

    uint32_t a[4][4][4];
#pragma unroll
    for (int mb = 0; mb < 4; ++mb) {
        int r0 = m0 + mhalf + mb * 16 + gid;
        int r1 = r0 + 8;
        const float* q0 = q + ((size_t)(b * LQ) + r0) * DH;
        const float* q1 = q + ((size_t)(b * LQ) + r1) * DH;
#pragma unroll
        for (int kk = 0; kk < 4; ++kk) {
            int c = kk * 16 + 2 * tig;
            float2 x0 = *(const float2*)(q0 + c);
            float2 x1 = *(const float2*)(q1 + c);
            float2 x2 = *(const float2*)(q0 + c + 8);
            float2 x3 = *(const float2*)(q1 + c + 8);
            a[mb][kk][0] = packbf(x0.x, x0.y);
            a[mb][kk][1] = packbf(x1.x, x1.y);
            a[mb][kk][2] = packbf(x2.x, x2.y);
            a[mb][kk][3] = packbf(x3.x, x3.y);
        }
    }

    const int niter = g_upad >> 7;
    uint32_t sBase = (uint32_t)__cvta_generic_to_shared(&Bs[0][0]);

    uint32_t rowoff[4];
#pragma unroll
    for (int nc = 0; nc < 4; ++nc) {
        int row = nquad * 32 + nc * 8 + (lane & 7);
        rowoff[nc] = (uint32_t)(row * 144 + (lane >> 3) * 16);
    }

    {   // prologue: tile 0
#pragma unroll
        for (int it2 = 0; it2 < 2; ++it2) {
            int unit = tid + 256 * it2;
            int row = unit >> 2, seg = unit & 3;
            const __nv_bfloat16* src = g_KsampH + ((size_t)(b * UPM) + row) * DH + seg * 16;
            uint32_t dst = sBase + row * 144 + seg * 32;
            cp16(dst, src);
            cp16(dst + 16, src + 8);
        }
    }
    asm volatile("cp.async.commit_group;\n");

    float rmax[4][2];
#pragma unroll
    for (int mb = 0; mb < 4; ++mb) { rmax[mb][0] = -INFINITY; rmax[mb][1] = -INFINITY; }

    for (int t = 0; t < niter; ++t) {
        asm volatile("cp.async.wait_group 0;\n");
        __syncthreads();
        if (t + 1 < niter) {
#pragma unroll
            for (int it2 = 0; it2 < 2; ++it2) {
                int unit = tid + 256 * it2;
                int row = unit >> 2, seg = unit & 3;
                const __nv_bfloat16* src =
                    g_KsampH + ((size_t)(b * UPM) + (t + 1) * 128 + row) * DH + seg * 16;
                uint32_t dst = sBase + ((t + 1) & 1) * 18432 + row * 144 + seg * 32;
                cp16(dst, src);
                cp16(dst + 16, src + 8);
            }
        }
        asm volatile("cp.async.commit_group;\n");

        uint32_t bufBase = sBase + (t & 1) * 18432;
#pragma unroll
        for (int nc = 0; nc < 4; ++nc) {
            uint32_t addr0 = bufBase + rowoff[nc];
            uint32_t bk[4], bk2[4];
            ldsm_x4(bk,  addr0);
            ldsm_x4(bk2, addr0 + 64);
#pragma unroll
            for (int mb = 0; mb < 4; ++mb) {
                float acc[4] = {0.f, 0.f, 0.f, 0.f};
                mma_bf16(acc, a[mb][0], bk[0],  bk[1]);
                mma_bf16(acc, a[mb][1], bk[2],  bk[3]);
                mma_bf16(acc, a[mb][2], bk2[0], bk2[1]);
                mma_bf16(acc, a[mb][3], bk2[2], bk2[3]);
                rmax[mb][0] = fmaxf(rmax[mb][0], fmaxf(acc[0], acc[1]));
                rmax[mb][1] = fmaxf(rmax[mb][1], fmaxf(acc[2], acc[3]));
            }
        }
    }

#pragma unroll
    for (int mb = 0; mb < 4; ++mb)
#pragma unroll
        for (int h = 0; h < 2; ++h) {
            rmax[mb][h] = fmaxf(rmax[mb][h], __shfl_xor_sync(0xffffffffu, rmax[mb][h], 1));
            rmax[mb][h] = fmaxf(rmax[mb][h], __shfl_xor_sync(0xffffffffu, rmax[mb][h], 2));
        }
    if (tig == 0) {
#pragma unroll
        for (int mb = 0; mb < 4; ++mb) {
            rowmaxS[nquad][mhalf + mb * 16 + gid]     = rmax[mb][0];
            rowmaxS[nquad][mhalf + mb * 16 + gid + 8] = rmax[mb][1];
        }
    }
    __syncthreads();

    if (tid < 128) {
        int m = m0 + tid;
        float mx = fmaxf(fmaxf(rowmaxS[0][tid], rowmaxS[1][tid]),
                         fmaxf(rowmaxS[2][tid], rowmaxS[3][tid]));
        const float* qp = q + ((size_t)(b * LQ) + m) * DH;
        float d0 = 0.f, d1 = 0.f, d2 = 0.f, d3 = 0.f;
#pragma unroll
        for (int d = 0; d < 64; d += 4) {
            d0 += qp[d]     * ksumS[d];
            d1 += qp[d + 1] * ksumS[d + 1];
            d2 += qp[d + 2] * ksumS[d + 2];
            d3 += qp[d + 3] * ksumS[d + 3];
        }
        g_M[b * LQ + m] = mx - ((d0 + d1) + (d2 + d3)) * (1.0f / (float)LKS);
    }
}

// ---------------- kernel 4: histogram threshold + candidate collect --------
__global__ __launch_bounds__(512) void k_thresh() {
    const int b = blockIdx.x;
    const int tid = threadIdx.x;
    __shared__ float sv[LQ];
    __shared__ int hist[512];
    __shared__ float wmn[16], wmx[16];
    __shared__ float s_mn, s_range, s_thresh;
    __shared__ int s_cnt;

    float mn = INFINITY, mx = -INFINITY;
    for (int j = tid; j < LQ; j += 512) {
        float v = g_M[b * LQ + j];
        sv[j] = v;
        mn = fminf(mn, v);
        mx = fmaxf(mx, v);
    }
#pragma unroll
    for (int off = 16; off > 0; off >>= 1) {
        mn = fminf(mn, __shfl_xor_sync(0xffffffffu, mn, off));
        mx = fmaxf(mx, __shfl_xor_sync(0xffffffffu, mx, off));
    }
    if ((tid & 31) == 0) { wmn[tid >> 5] = mn; wmx[tid >> 5] = mx; }
    if (tid < 512) hist[tid] = 0;
    if (tid == 0) s_cnt = 0;
    __syncthreads();
    if (tid == 0) {
        float a = INFINITY, z = -INFINITY;
        for (int g = 0; g < 16; ++g) { a = fminf(a, wmn[g]); z = fmaxf(z, wmx[g]); }
        s_mn = a;
        s_range = z - a + 1e-6f;
    }
    __syncthreads();
    const float scale = 511.0f / s_range;
    for (int j = tid; j < LQ; j += 512) {
        int bin = (int)((sv[j] - s_mn) * scale);
        bin = max(0, min(511, bin));
        atomicAdd(&hist[bin], 1);
    }
    __syncthreads();
    if (tid == 0) {
        int cum = 0, bsel = 511;
        for (int i = 0; i < 512; ++i) {
            cum += hist[i];
            if (cum >= NU) { bsel = i; break; }
        }
        s_thresh = s_mn + (float)(bsel + 1) * (s_range / 511.0f) + MARGIN;
    }
    __syncthreads();
    const float th = s_thresh;
    for (int j = tid; j < LQ; j += 512) {
        if (sv[j] <= th) {
            int p = atomicAdd(&s_cnt, 1);
            if (p < CANDMAX) g_cand[b * CANDMAX + p] = j;
        }
    }
    __syncthreads();
    if (tid == 0) g_ccount[b] = min(s_cnt, CANDMAX);
}

// ---------------- kernel 5: exact fp32 max (split-K over unique keys) ------
__global__ __launch_bounds__(256) void k_M_exact(const float* __restrict__ q,
                                                 const float* __restrict__ K) {
    extern __shared__ float sh[];
    float* Kc = sh;                       // [KROWS][68]
    float* Qc = sh + KROWS * 68;          // [128][68]

    const int b = blockIdx.y;
    const int sp = blockIdx.x;
    const int tid = threadIdx.x;
    const int wid = tid >> 5;
    const int lane = tid & 31;

    const int uc = g_ucount;
    const int j0 = (sp * uc) / NSPLIT;
    const int j1 = ((sp + 1) * uc) / NSPLIT;
    const int cnt = g_ccount[b];

    for (int kc = j0, first = 1; kc < j1; kc += KROWS, first = 0) {
        const int nr = min(KROWS, j1 - kc);
        __syncthreads();
        for (int i = tid; i < nr * 16; i += 256) {
            int r = i >> 4, d4 = i & 15;
            int src = g_uniq[kc + r];
            *(float4*)&Kc[r * 68 + 4 * d4] =
                *(const float4*)(K + ((size_t)b * LK + src) * DH + 4 * d4);
        }

        for (int cg = 0; cg < cnt; cg += 128) {
            int ncg = min(128, cnt - cg);
            __syncthreads();
            for (int i = tid; i < ncg * 16; i += 256) {
                int c = i >> 4, d4 = i & 15;
                int qi = g_cand[b * CANDMAX + cg + c];
                *(float4*)&Qc[c * 68 + 4 * d4] =
                    *(const float4*)(q + ((size_t)(b * LQ) + qi) * DH + 4 * d4);
            }
            __syncthreads();
            for (int c = wid; c < ncg; c += 8) {
                const float* qr = &Qc[c * 68];
                float mx = -INFINITY;
                for (int r = lane; r < nr; r += 32) {
                    const float* kr = &Kc[r * 68];
                    float a0 = 0.f, a1 = 0.f, a2 = 0.f, a3 = 0.f;
#pragma unroll
                    for (int d4 = 0; d4 < 16; ++d4) {
                        float4 kv = *(const float4*)&kr[4 * d4];
                        float4 qv = *(const float4*)&qr[4 * d4];
                        a0 += qv.x * kv.x;
                        a1 += qv.y * kv.y;
                        a2 += qv.z * kv.z;
                        a3 += qv.w * kv.w;
                    }
                    mx = fmaxf(mx, (a0 + a1) + (a2 + a3));
                }
#pragma unroll
                for (int off = 16; off > 0; off >>= 1)
                    mx = fmaxf(mx, __shfl_xor_sync(0xffffffffu, mx, off));
                if (lane == 0) {
                    float* slot = &g_candP[((size_t)(b * CANDMAX) + cg + c) * NSPLIT + sp];
                    *slot = first ? mx : fmaxf(*slot, mx);
                }
            }
        }
    }
}

// ---------------- kernel 6: finalize exact M + top-45 selection ------------
__global__ __launch_bounds__(256) void k_select(const float* __restrict__ q) {
    const int b = blockIdx.x;
    const int tid = threadIdx.x;
    __shared__ float cv[CANDMAX];
    __shared__ int   ci[CANDMAX];
    __shared__ float ksumS[64];
    const int cnt = g_ccount[b];

    if (tid < 64) {
        float s = 0.f;
        for (int i = 0; i < GPB; ++i) s += g_Kpart[((size_t)b * GPB + i) * DH + tid];
        ksumS[tid] = s;
    }
    __syncthreads();

    for (int c = tid; c < CANDMAX; c += 256) {
        if (c < cnt) {
            float mx = -INFINITY;
#pragma unroll
            for (int s = 0; s < NSPLIT; ++s)
                mx = fmaxf(mx, g_candP[((size_t)(b * CANDMAX) + c) * NSPLIT + s]);
            int qi = g_cand[b * CANDMAX + c];
            const float* qp = q + ((size_t)(b * LQ) + qi) * DH;
            float dot = 0.f;
            for (int d = 0; d < 64; ++d) dot += qp[d] * ksumS[d];
            cv[c] = mx - dot * (1.0f / (float)LKS);
            ci[c] = qi;
        } else {
            cv[c] = INFINITY;
            ci[c] = 1 << 30;
        }
    }
    __syncthreads();

    if (tid < 32) {
        for (int it = 0; it < NU; ++it) {
            float best = INFINITY; int bidx = 1 << 30; int bslot = 0;
            for (int j = tid; j < CANDMAX; j += 32) {
                float v = cv[j]; int qi2 = ci[j];
                if (v < best || (v == best && qi2 < bidx)) { best = v; bidx = qi2; bslot = j; }
            }
#pragma unroll
            for (int off = 16; off > 0; off >>= 1) {
                float v2 = __shfl_xor_sync(0xffffffffu, best, off);
                int   i2 = __shfl_xor_sync(0xffffffffu, bidx, off);
                int   s2 = __shfl_xor_sync(0xffffffffu, bslot, off);
                if (v2 < best || (v2 == best && i2 < bidx)) { best = v2; bidx = i2; bslot = s2; }
            }
            if (tid == 0) { g_top[b * NUP + it] = bidx; cv[bslot] = INFINITY; }
            __syncwarp();
        }
        if (tid < NUP - NU) g_top[b * NUP + NU + tid] = 0;
    }
}

// ---------------- kernel 7: bf16x2-Karatsuba mma attention (single wave) ---
__global__ __launch_bounds__(256, 3) void k_attn(const float* __restrict__ q,
                                                 const float* __restrict__ K,
                                                 const float* __restrict__ V,
                                                 float* __restrict__ out_s) {
    extern __shared__ char smc[];
    __nv_bfloat16* Qh = (__nv_bfloat16*)smc;            // 48*72
    __nv_bfloat16* Ql = Qh + 48 * 72;
    __nv_bfloat16* Kh = Ql + 48 * 72;                   // 64*72
    __nv_bfloat16* Kl = Kh + 64 * 72;
    __nv_bfloat16* Vh = Kl + 64 * 72;                   // 64*72 rows=key
    __nv_bfloat16* Vl = Vh + 64 * 72;
    char* Ub = (char*)(Vl + 64 * 72);                   // union, 13824 B
    float* SP = (float*)Ub;                             // [48][68] f32
    __nv_bfloat16* Ph = (__nv_bfloat16*)Ub;             // [48][72]
    __nv_bfloat16* Pl = Ph + 48 * 72;
    float* fS = (float*)(Ub + 13824);                   // [48]

    const uint32_t sQh = (uint32_t)__cvta_generic_to_shared(Qh);
    const uint32_t sQl = (uint32_t)__cvta_generic_to_shared(Ql);
    const uint32_t sKh = (uint32_t)__cvta_generic_to_shared(Kh);
    const uint32_t sKl = (uint32_t)__cvta_generic_to_shared(Kl);
    const uint32_t sVh = (uint32_t)__cvta_generic_to_shared(Vh);
    const uint32_t sVl = (uint32_t)__cvta_generic_to_shared(Vl);
    const uint32_t sPh = (uint32_t)__cvta_generic_to_shared(Ph);
    const uint32_t sPl = (uint32_t)__cvta_generic_to_shared(Pl);

    const int tid = threadIdx.x;
    const int ty = tid >> 5;
    const int tx = tid & 31;
    const int gid = tx >> 2;
    const int tig = tx & 3;
    const int b = blockIdx.y;
    const int chunk = blockIdx.x;
    const int t0 = (chunk * NTILES) / NCHUNK;
    const int t1 = ((chunk + 1) * NTILES) / NCHUNK;

#pragma unroll
    for (int i = 0; i < 3; ++i) {
        int fidx = tid + 256 * i;
        int u    = fidx >> 4;
        int d4   = fidx & 15;
        float4 v = make_float4(0.f, 0.f, 0.f, 0.f);
        if (u < NU) {
            int qi = g_top[b * NUP + u];
            v = *(const float4*)(q + ((size_t)(b * LQ + qi)) * DH + 4 * d4);
        }
        uint32_t h0, l0, h1, l1;
        bfsplit2(v.x, v.y, h0, l0);
        bfsplit2(v.z, v.w, h1, l1);
        *(uint32_t*)(Qh + u * 72 + 4 * d4)     = h0;
        *(uint32_t*)(Qh + u * 72 + 4 * d4 + 2) = h1;
        *(uint32_t*)(Ql + u * 72 + 4 * d4)     = l0;
        *(uint32_t*)(Ql + u * 72 + 4 * d4 + 2) = l1;
    }

    float mrun[6], lrun[6];
#pragma unroll
    for (int i = 0; i < 6; ++i) { mrun[i] = -INFINITY; lrun[i] = 0.f; }
    float oc[3][4];
#pragma unroll
    for (int mt = 0; mt < 3; ++mt)
#pragma unroll
        for (int i = 0; i < 4; ++i) oc[mt][i] = 0.f;

    for (int kt = t0; kt < t1; ++kt) {
        const int kg0 = kt * KT;
        __syncthreads();
#pragma unroll
        for (int i = 0; i < 4; ++i) {
            int fidx = tid + 256 * i;
            int k    = fidx >> 4;
            int d4   = fidx & 15;
            float4 kv = *(const float4*)(K + ((size_t)(b * LK + kg0 + k)) * DH + 4 * d4);
            uint32_t h0, l0, h1, l1;
            bfsplit2(kv.x, kv.y, h0, l0);
            bfsplit2(kv.z, kv.w, h1, l1);
            *(uint32_t*)(Kh + k * 72 + 4 * d4)     = h0;
            *(uint32_t*)(Kh + k * 72 + 4 * d4 + 2) = h1;
            *(uint32_t*)(Kl + k * 72 + 4 * d4)     = l0;
            *(uint32_t*)(Kl + k * 72 + 4 * d4 + 2) = l1;
            float4 vv = *(const float4*)(V + ((size_t)(b * LK + kg0 + k)) * DH + 4 * d4);
            bfsplit2(vv.x, vv.y, h0, l0);
            bfsplit2(vv.z, vv.w, h1, l1);
            *(uint32_t*)(Vh + k * 72 + 4 * d4)     = h0;
            *(uint32_t*)(Vh + k * 72 + 4 * d4 + 2) = h1;
            *(uint32_t*)(Vl + k * 72 + 4 * d4)     = l0;
            *(uint32_t*)(Vl + k * 72 + 4 * d4 + 2) = l1;
        }
        __syncthreads();

        {
            uint32_t bh[8], bl[8];
            uint32_t kaddr = sKh + (uint32_t)((8 * ty + (tx & 7)) * 144 + (tx >> 3) * 16);
            ldsm_x4(bh,     kaddr);
            ldsm_x4(bh + 4, kaddr + 64);
            kaddr = sKl + (uint32_t)((8 * ty + (tx & 7)) * 144 + (tx >> 3) * 16);
            ldsm_x4(bl,     kaddr);
            ldsm_x4(bl + 4, kaddr + 64);

#pragma unroll
            for (int mt = 0; mt < 3; ++mt) {
                float accS[4] = {0.f, 0.f, 0.f, 0.f};
                uint32_t arow = (uint32_t)((mt * 16 + (tx & 15)) * 144 + (tx >> 4) * 16);
#pragma unroll
                for (int ks = 0; ks < 4; ++ks) {
                    uint32_t ah[4], al[4];
                    ldsm_x4(ah, sQh + arow + ks * 32);
                    ldsm_x4(al, sQl + arow + ks * 32);
                    mma_bf16(accS, ah, bh[2 * ks], bh[2 * ks + 1]);
                    mma_bf16(accS, ah, bl[2 * ks], bl[2 * ks + 1]);
                    mma_bf16(accS, al, bh[2 * ks], bh[2 * ks + 1]);
                }
                int r0 = mt * 16 + gid;
                *(float2*)&SP[r0 * 68 + 8 * ty + 2 * tig] =
                    make_float2(accS[0] * 0.125f, accS[1] * 0.125f);
                *(float2*)&SP[(r0 + 8) * 68 + 8 * ty + 2 * tig] =
                    make_float2(accS[2] * 0.125f, accS[3] * 0.125f);
            }
        }
        __syncthreads();

        float pr[6][2], fnew[6];
#pragma unroll
        for (int i = 0; i < 6; ++i) {
            int u = 6 * ty + i;
            float2 sv = *(const float2*)&SP[u * 68 + 2 * tx];
            float mx = fmaxf(sv.x, sv.y);
#pragma unroll
            for (int off = 16; off > 0; off >>= 1)
                mx = fmaxf(mx, __shfl_xor_sync(0xffffffffu, mx, off));
            float mn = fmaxf(mrun[i], mx);
            float f  = __expf(mrun[i] - mn);
            float p0 = __expf(sv.x - mn);
            float p1 = __expf(sv.y - mn);
            float ps = p0 + p1;
#pragma unroll
            for (int off = 16; off > 0; off >>= 1)
                ps += __shfl_xor_sync(0xffffffffu, ps, off);
            lrun[i] = lrun[i] * f + ps;
            mrun[i] = mn;
            fnew[i] = f;
            pr[i][0] = p0; pr[i][1] = p1;
            if (u < NU)
                *(float2*)(out_s + ((size_t)(b * NU + u)) * LK + kg0 + 2 * tx) = sv;
        }
        __syncthreads();

#pragma unroll
        for (int i = 0; i < 6; ++i) {
            int u = 6 * ty + i;
            uint32_t h, l;
            bfsplit2(pr[i][0], pr[i][1], h, l);
            *(uint32_t*)(Ph + u * 72 + 2 * tx) = h;
            *(uint32_t*)(Pl + u * 72 + 2 * tx) = l;
            if (tx == 0) fS[u] = fnew[i];
        }
        __syncthreads();

        {
            uint32_t bh[8], bl[8];
            uint32_t vaddr = sVh + (uint32_t)(tx * 144 + 16 * ty);
            ldsm_x4_t(bh,     vaddr);
            ldsm_x4_t(bh + 4, vaddr + 32 * 144);
            vaddr = sVl + (uint32_t)(tx * 144 + 16 * ty);
            ldsm_x4_t(bl,     vaddr);
            ldsm_x4_t(bl + 4, vaddr + 32 * 144);

#pragma unroll
            for (int mt = 0; mt < 3; ++mt) {
                float f0 = fS[mt * 16 + gid];
                float f1 = fS[mt * 16 + gid + 8];
                oc[mt][0] *= f0; oc[mt][1] *= f0;
                oc[mt][2] *= f1; oc[mt][3] *= f1;
                uint32_t arow = (uint32_t)((mt * 16 + (tx & 15)) * 144 + (tx >> 4) * 16);
#pragma unroll
                for (int ks = 0; ks < 4; ++ks) {
                    uint32_t ph[4], pl2[4];
                    ldsm_x4(ph,  sPh + arow + ks * 32);
                    ldsm_x4(pl2, sPl + arow + ks * 32);
                    mma_bf16(oc[mt], ph,  bh[2 * ks], bh[2 * ks + 1]);
                    mma_bf16(oc[mt], ph,  bl[2 * ks], bl[2 * ks + 1]);
                    mma_bf16(oc[mt], pl2, bh[2 * ks], bh[2 * ks + 1]);
                }
            }
        }
    }

    if (tx == 0) {
#pragma unroll
        for (int i = 0; i < 6; ++i) {
            int u = 6 * ty + i;
            g_pm[(b * NCHUNK + chunk) * NUP + u] = mrun[i];
            g_pl[(b * NCHUNK + chunk) * NUP + u] = lrun[i];
        }
    }
#pragma unroll
    for (int mt = 0; mt < 3; ++mt) {
        int r0 = mt * 16 + gid;
        *(float2*)&g_pacc[((size_t)(b * NCHUNK + chunk) * NUP + r0) * DH + 8 * ty + 2 * tig] =
            make_float2(oc[mt][0], oc[mt][1]);
        *(float2*)&g_pacc[((size_t)(b * NCHUNK + chunk) * NUP + r0 + 8) * DH + 8 * ty + 2 * tig] =
            make_float2(oc[mt][2], oc[mt][3]);
    }
}

// ---------------- kernel 8: combine split-softmax partials ----------------
__global__ void k_combine(float* __restrict__ out_o) {
    int u = blockIdx.x;
    int b = blockIdx.y;
    int d = threadIdx.x;
    float gm = -INFINITY;
    for (int c = 0; c < NCHUNK; ++c)
        gm = fmaxf(gm, g_pm[(b * NCHUNK + c) * NUP + u]);
    float L = 0.f, a = 0.f;
    for (int c = 0; c < NCHUNK; ++c) {
        float w = __expf(g_pm[(b * NCHUNK + c) * NUP + u] - gm);
        L += g_pl[(b * NCHUNK + c) * NUP + u] * w;
        a += g_pacc[((size_t)(b * NCHUNK + c) * NUP + u) * DH + d] * w;
    }
    out_o[(b * NU + u) * DH + d] = a / L;
}

// ---------------- launch ----------------
extern "C" void kernel_launch(void* const* d_in, const int* in_sizes, int n_in,
                              void* d_out, int out_size) {
    const float* q  = (const float*)d_in[0];
    const float* K  = (const float*)d_in[1];
    const float* V  = (const float*)d_in[2];
    const int* idx  = (const int*)d_in[3];
    float* out_o = (float*)d_out;                  // attn_output [8,45,64]
    float* out_s = out_o + NB * NU * DH;           // attn_scores [8,45,32768]

    (void)in_sizes; (void)n_in; (void)out_size;

    const int smem_attn  = 48 * 72 * 2 * 2 + 64 * 72 * 2 * 2 * 2 + 13824 + 192;  // 64704
    const int smem_exact = (KROWS * 68 + 128 * 68) * 4;                          // 82688
    cudaFuncSetAttribute(k_attn,    cudaFuncAttributeMaxDynamicSharedMemorySize, smem_attn);
    cudaFuncSetAttribute(k_M_exact, cudaFuncAttributeMaxDynamicSharedMemorySize, smem_exact);

    k_dedup<<<1, 1024>>>(idx);
    k_gather<<<NB * GPB, 256>>>(K);
    k_M_mma<<<dim3(LQ / 128, NB), 256>>>(q);
    k_thresh<<<NB, 512>>>();
    k_M_exact<<<dim3(NSPLIT, NB), 256, smem_exact>>>(q, K);
    k_select<<<NB, 256>>>(q);
    k_attn<<<dim3(NCHUNK, NB), 256, smem_attn>>>(q, K, V, out_s);
    k_combine<<<dim3(NU, NB), 64>>>(out_o);
}